// round 10
// baseline (speedup 1.0000x reference)
#include <cuda_runtime.h>
#include <cuda_bf16.h>
#include <math.h>
#include <stdint.h>

// Problem constants
#define BB 4
#define SS 1024
#define EE 1024
#define DD 1024
#define HH 16
#define DHH 64
#define DFF 4096
#define LN_EPS 1e-6f

// ----------------------------------------------------------------------------
// Scratch (static device globals; no allocations allowed)
// ----------------------------------------------------------------------------
__device__ float g_q   [BB * SS * DD];
__device__ float g_qkv [BB * SS * 3 * DD];      // fused QKV / KV outputs
__device__ float g_wpk [3 * DD * DD + 4 * DD];  // packed weights + biases
__device__ float g_ctx [BB * SS * DD];
__device__ float g_t0  [BB * SS * DD];
__device__ float g_x1  [BB * SS * DD];
__device__ float g_y   [BB * SS * DD];
__device__ float g_ffn [BB * SS * DFF];
__device__ float g_scores[(size_t)BB * HH * SS * SS];

// ----------------------------------------------------------------------------
// TF32 mma helpers (RNA rounding on all operands — unbiased).
// ----------------------------------------------------------------------------
__device__ __forceinline__ unsigned cvt_tf32(float x) {
    unsigned r;
    asm("cvt.rna.tf32.f32 %0, %1;" : "=r"(r) : "f"(x));
    return r;
}

__device__ __forceinline__ void mma_tf32(float* d, const unsigned* a,
                                         const unsigned* b, const float* c) {
    asm("mma.sync.aligned.m16n8k8.row.col.f32.tf32.tf32.f32 "
        "{%0,%1,%2,%3}, {%4,%5,%6,%7}, {%8,%9}, {%10,%11,%12,%13};"
        : "=f"(d[0]), "=f"(d[1]), "=f"(d[2]), "=f"(d[3])
        : "r"(a[0]), "r"(a[1]), "r"(a[2]), "r"(a[3]),
          "r"(b[0]), "r"(b[1]),
          "f"(c[0]), "f"(c[1]), "f"(c[2]), "f"(c[3]));
}

__device__ __forceinline__ void cp_async16(void* smem, const void* gmem) {
    unsigned saddr = (unsigned)__cvta_generic_to_shared(smem);
    asm volatile("cp.async.cg.shared.global [%0], [%1], 16;" :: "r"(saddr), "l"(gmem));
}
#define CP_COMMIT() asm volatile("cp.async.commit_group;")
__device__ __forceinline__ void cp_wait0() { asm volatile("cp.async.wait_group 0;"); }
__device__ __forceinline__ void cp_wait1() { asm volatile("cp.async.wait_group 1;"); }

// ----------------------------------------------------------------------------
// Strided column copy: dst[r*ldD + c] = src[r*C + c], r in [0,R), c in [0,C)
// ----------------------------------------------------------------------------
__global__ __launch_bounds__(256) void copy_cols_kernel(
    const float* __restrict__ src, float* __restrict__ dst, int R, int C, int ldD)
{
    int c = blockIdx.x * 256 + threadIdx.x;
    int r = blockIdx.y;
    if (c < C) dst[(size_t)r * ldD + c] = src[(size_t)r * C + c];
}

// ----------------------------------------------------------------------------
// TF32 GEMM, 2-stage cp.async pipeline.
// C[M,N] = A[M,K] @ B[K,N] + bias[N], optional ReLU.
// 128x128x32 CTA tile, 8 warps (4m x 2n), warp tile 32x64.
// ----------------------------------------------------------------------------
#define GEMM_SMEM (2 * (128 * 36 + 32 * 136) * 4)
#define AS_OFF(st) ((st) * 128 * 36)
#define BS_OFF(st) (2 * 128 * 36 + (st) * 32 * 136)

template <int RELU>
__global__ __launch_bounds__(256, 2) void gemm_tf32_kernel(
    const float* __restrict__ A, const float* __restrict__ B,
    const float* __restrict__ bias, float* __restrict__ C,
    int M, int N, int K)
{
    extern __shared__ float sm[];

    const int tid  = threadIdx.x;
    const int wid  = tid >> 5;
    const int lane = tid & 31;
    const int g    = lane >> 2;
    const int tig  = lane & 3;
    const int warpM = wid & 3;
    const int warpN = wid >> 2;
    const int m0 = blockIdx.y * 128;
    const int n0 = blockIdx.x * 128;

    float acc[2][8][4];
#pragma unroll
    for (int mt = 0; mt < 2; mt++)
#pragma unroll
        for (int nt = 0; nt < 8; nt++)
#pragma unroll
            for (int i = 0; i < 4; i++) acc[mt][nt][i] = 0.f;

    auto load_stage = [&](int st, int k0) {
        float* As = sm + AS_OFF(st);
        float* Bs = sm + BS_OFF(st);
#pragma unroll
        for (int l = 0; l < 4; l++) {
            int idx = tid + l * 256;
            int m = idx >> 3, s = idx & 7;
            cp_async16(&As[m * 36 + s * 4], &A[(size_t)(m0 + m) * K + k0 + s * 4]);
        }
#pragma unroll
        for (int l = 0; l < 4; l++) {
            int idx = tid + l * 256;
            int kk = idx >> 5, s = idx & 31;
            cp_async16(&Bs[kk * 136 + s * 4], &B[(size_t)(k0 + kk) * N + n0 + s * 4]);
        }
        CP_COMMIT();
    };

    const int T = K >> 5;
    load_stage(0, 0);

    for (int t = 0; t < T; t++) {
        if (t + 1 < T) { load_stage((t + 1) & 1, (t + 1) << 5); cp_wait1(); }
        else           { cp_wait0(); }
        __syncthreads();

        const float* As = sm + AS_OFF(t & 1);
        const float* Bs = sm + BS_OFF(t & 1);
#pragma unroll
        for (int kk = 0; kk < 32; kk += 8) {
            unsigned af[2][4];
#pragma unroll
            for (int mt = 0; mt < 2; mt++) {
                int r = warpM * 32 + mt * 16 + g;
                af[mt][0] = cvt_tf32(As[r * 36 + kk + tig]);
                af[mt][1] = cvt_tf32(As[(r + 8) * 36 + kk + tig]);
                af[mt][2] = cvt_tf32(As[r * 36 + kk + tig + 4]);
                af[mt][3] = cvt_tf32(As[(r + 8) * 36 + kk + tig + 4]);
            }
            unsigned bf[8][2];
#pragma unroll
            for (int nt = 0; nt < 8; nt++) {
                int c = warpN * 64 + nt * 8 + g;
                bf[nt][0] = cvt_tf32(Bs[(kk + tig) * 136 + c]);
                bf[nt][1] = cvt_tf32(Bs[(kk + tig + 4) * 136 + c]);
            }
#pragma unroll
            for (int mt = 0; mt < 2; mt++)
#pragma unroll
                for (int nt = 0; nt < 8; nt++)
                    mma_tf32(acc[mt][nt], af[mt], bf[nt], acc[mt][nt]);
        }
        __syncthreads();
    }

#pragma unroll
    for (int mt = 0; mt < 2; mt++) {
        int r0 = m0 + warpM * 32 + mt * 16 + g;
#pragma unroll
        for (int nt = 0; nt < 8; nt++) {
            int c0 = n0 + warpN * 64 + nt * 8 + tig * 2;
            float b0 = bias[c0], b1 = bias[c0 + 1];
            float v0 = acc[mt][nt][0] + b0;
            float v1 = acc[mt][nt][1] + b1;
            float v2 = acc[mt][nt][2] + b0;
            float v3 = acc[mt][nt][3] + b1;
            if (RELU) {
                v0 = fmaxf(v0, 0.f); v1 = fmaxf(v1, 0.f);
                v2 = fmaxf(v2, 0.f); v3 = fmaxf(v3, 0.f);
            }
            *reinterpret_cast<float2*>(&C[(size_t)r0 * N + c0])       = make_float2(v0, v1);
            *reinterpret_cast<float2*>(&C[(size_t)(r0 + 8) * N + c0]) = make_float2(v2, v3);
        }
    }
}

// ----------------------------------------------------------------------------
// Attention scores (TF32 mma): S[bh,q,k] = (Q . K)*0.125 + mask*(-1e9)
// Q/K consumed with arbitrary row stride (supports packed QKV buffers).
// Causal fully-masked tiles (k0 > q0+127): no work, no store.
// ----------------------------------------------------------------------------
#define SCORES_SMEM (2 * 128 * 68 * 4)

__global__ __launch_bounds__(256, 2) void attn_scores_tf32(
    const float* __restrict__ Qf, int ldq,
    const float* __restrict__ Kf, int ldk,
    const float* __restrict__ pmask, int mask_mode,
    float* __restrict__ Sout, int Sq, int Skv)
{
    extern __shared__ float sm[];
    float* Qs = sm;
    float* Ks = sm + 128 * 68;

    const int tid  = threadIdx.x;
    const int wid  = tid >> 5;
    const int lane = tid & 31;
    const int g    = lane >> 2;
    const int tig  = lane & 3;
    const int warpM = wid & 3;
    const int warpN = wid >> 2;
    const int bh = blockIdx.z;
    const int b = bh >> 4, h = bh & 15;
    const int q0 = blockIdx.y * 128;
    const int k0 = blockIdx.x * 128;

    if (mask_mode == 0 && k0 > q0 + 127) return;

#pragma unroll
    for (int l = 0; l < 8; l++) {
        int idx = tid + l * 256;
        int m = idx >> 4, s = idx & 15;
        cp_async16(&Qs[m * 68 + s * 4],
                   &Qf[(size_t)(b * Sq + q0 + m) * ldq + h * DHH + s * 4]);
    }
#pragma unroll
    for (int l = 0; l < 8; l++) {
        int idx = tid + l * 256;
        int m = idx >> 4, s = idx & 15;
        cp_async16(&Ks[m * 68 + s * 4],
                   &Kf[(size_t)(b * Skv + k0 + m) * ldk + h * DHH + s * 4]);
    }
    CP_COMMIT();
    cp_wait0();
    __syncthreads();

    float acc[2][8][4];
#pragma unroll
    for (int mt = 0; mt < 2; mt++)
#pragma unroll
        for (int nt = 0; nt < 8; nt++)
#pragma unroll
            for (int i = 0; i < 4; i++) acc[mt][nt][i] = 0.f;

#pragma unroll
    for (int kk = 0; kk < 64; kk += 8) {
        unsigned af[2][4];
#pragma unroll
        for (int mt = 0; mt < 2; mt++) {
            int r = warpM * 32 + mt * 16 + g;
            af[mt][0] = cvt_tf32(Qs[r * 68 + kk + tig]);
            af[mt][1] = cvt_tf32(Qs[(r + 8) * 68 + kk + tig]);
            af[mt][2] = cvt_tf32(Qs[r * 68 + kk + tig + 4]);
            af[mt][3] = cvt_tf32(Qs[(r + 8) * 68 + kk + tig + 4]);
        }
        unsigned bf[8][2];
#pragma unroll
        for (int nt = 0; nt < 8; nt++) {
            int r = warpN * 64 + nt * 8 + g;
            bf[nt][0] = cvt_tf32(Ks[r * 68 + kk + tig]);
            bf[nt][1] = cvt_tf32(Ks[r * 68 + kk + tig + 4]);
        }
#pragma unroll
        for (int mt = 0; mt < 2; mt++)
#pragma unroll
            for (int nt = 0; nt < 8; nt++)
                mma_tf32(acc[mt][nt], af[mt], bf[nt], acc[mt][nt]);
    }

#pragma unroll
    for (int mt = 0; mt < 2; mt++) {
        int qr0 = q0 + warpM * 32 + mt * 16 + g;
#pragma unroll
        for (int nt = 0; nt < 8; nt++) {
            int kc0 = k0 + warpN * 64 + nt * 8 + tig * 2;
#pragma unroll
            for (int half = 0; half < 2; half++) {
                int q = qr0 + half * 8;
                float v0 = acc[mt][nt][half * 2 + 0] * 0.125f;
                float v1 = acc[mt][nt][half * 2 + 1] * 0.125f;
                if (mask_mode == 0) {
                    if (kc0 > q)     v0 -= 1e9f;
                    if (kc0 + 1 > q) v1 -= 1e9f;
                } else {
                    v0 += pmask[(size_t)b * Skv + kc0] * (-1e9f);
                    v1 += pmask[(size_t)b * Skv + kc0 + 1] * (-1e9f);
                }
                *reinterpret_cast<float2*>(&Sout[((size_t)bh * Sq + q) * Skv + kc0]) =
                    make_float2(v0, v1);
            }
        }
    }
}

// ----------------------------------------------------------------------------
// Row softmax, ncols = 1024. One warp per row.
// causal != 0: row q reads only written chunks (k <= q), zero-fills the rest.
// ----------------------------------------------------------------------------
__global__ __launch_bounds__(256) void softmax_rows_kernel(
    float* __restrict__ P, int nrows, int causal)
{
    int row = blockIdx.x * 8 + threadIdx.y;
    if (row >= nrows) return;
    float* p = P + (size_t)row * 1024;
    const int lane = threadIdx.x;
    const int q = row & (SS - 1);
    const int nChunk = causal ? ((q >> 5) + 1) : 32;

    float v[32];
    float mx = -INFINITY;
    for (int i = 0; i < nChunk; i++) {
        v[i] = p[lane + i * 32];
        mx = fmaxf(mx, v[i]);
    }
#pragma unroll
    for (int o = 16; o; o >>= 1) mx = fmaxf(mx, __shfl_xor_sync(0xffffffffu, mx, o));

    float sum = 0.f;
    for (int i = 0; i < nChunk; i++) {
        v[i] = __expf(v[i] - mx);
        sum += v[i];
    }
#pragma unroll
    for (int o = 16; o; o >>= 1) sum += __shfl_xor_sync(0xffffffffu, sum, o);
    float inv = 1.f / sum;
    for (int i = 0; i < nChunk; i++) p[lane + i * 32] = v[i] * inv;
    for (int i = nChunk; i < 32; i++) p[lane + i * 32] = 0.f;
}

// ----------------------------------------------------------------------------
// attn_v (TF32 mma, 2-stage pipeline): ctx = P @ V  (per (b,h))
// V consumed with arbitrary row stride ldv.
// ----------------------------------------------------------------------------
#define ATTNV_SMEM (2 * (128 * 36 + 32 * 72) * 4)
#define PS_OFF(st) ((st) * 128 * 36)
#define VS_OFF(st) (2 * 128 * 36 + (st) * 32 * 72)

__global__ __launch_bounds__(256, 2) void attn_v_tf32(
    const float* __restrict__ P, const float* __restrict__ Vf, int ldv,
    float* __restrict__ ctx, int Sq, int Skv, int mask_mode)
{
    extern __shared__ float sm[];

    const int tid  = threadIdx.x;
    const int wid  = tid >> 5;
    const int lane = tid & 31;
    const int g    = lane >> 2;
    const int tig  = lane & 3;
    const int warpM = wid & 3;
    const int warpN = wid >> 2;
    const int bh = blockIdx.y;
    const int b = bh >> 4, h = bh & 15;
    const int q0 = blockIdx.x * 128;

    const int kEnd = (mask_mode == 0) ? min(Skv, q0 + 128) : Skv;
    const int T = kEnd >> 5;

    float acc[2][4][4];
#pragma unroll
    for (int mt = 0; mt < 2; mt++)
#pragma unroll
        for (int nt = 0; nt < 4; nt++)
#pragma unroll
            for (int i = 0; i < 4; i++) acc[mt][nt][i] = 0.f;

    auto load_stage = [&](int st, int k0) {
        float* Ps = sm + PS_OFF(st);
        float* Vs = sm + VS_OFF(st);
#pragma unroll
        for (int l = 0; l < 4; l++) {
            int idx = tid + l * 256;
            int m = idx >> 3, s = idx & 7;
            cp_async16(&Ps[m * 36 + s * 4],
                       &P[((size_t)bh * Sq + q0 + m) * Skv + k0 + s * 4]);
        }
#pragma unroll
        for (int l = 0; l < 2; l++) {
            int idx = tid + l * 256;
            int kk = idx >> 4, s = idx & 15;
            cp_async16(&Vs[kk * 72 + s * 4],
                       &Vf[(size_t)(b * Skv + k0 + kk) * ldv + h * DHH + s * 4]);
        }
        CP_COMMIT();
    };

    load_stage(0, 0);

    for (int t = 0; t < T; t++) {
        if (t + 1 < T) { load_stage((t + 1) & 1, (t + 1) << 5); cp_wait1(); }
        else           { cp_wait0(); }
        __syncthreads();

        const float* Ps = sm + PS_OFF(t & 1);
        const float* Vs = sm + VS_OFF(t & 1);
#pragma unroll
        for (int kk = 0; kk < 32; kk += 8) {
            unsigned af[2][4];
#pragma unroll
            for (int mt = 0; mt < 2; mt++) {
                int r = warpM * 32 + mt * 16 + g;
                af[mt][0] = cvt_tf32(Ps[r * 36 + kk + tig]);
                af[mt][1] = cvt_tf32(Ps[(r + 8) * 36 + kk + tig]);
                af[mt][2] = cvt_tf32(Ps[r * 36 + kk + tig + 4]);
                af[mt][3] = cvt_tf32(Ps[(r + 8) * 36 + kk + tig + 4]);
            }
            unsigned bf[4][2];
#pragma unroll
            for (int nt = 0; nt < 4; nt++) {
                int c = warpN * 32 + nt * 8 + g;
                bf[nt][0] = cvt_tf32(Vs[(kk + tig) * 72 + c]);
                bf[nt][1] = cvt_tf32(Vs[(kk + tig + 4) * 72 + c]);
            }
#pragma unroll
            for (int mt = 0; mt < 2; mt++)
#pragma unroll
                for (int nt = 0; nt < 4; nt++)
                    mma_tf32(acc[mt][nt], af[mt], bf[nt], acc[mt][nt]);
        }
        __syncthreads();
    }

#pragma unroll
    for (int mt = 0; mt < 2; mt++) {
        int qr0 = q0 + warpM * 32 + mt * 16 + g;
#pragma unroll
        for (int nt = 0; nt < 4; nt++) {
            int c0 = warpN * 32 + nt * 8 + tig * 2;
            *reinterpret_cast<float2*>(
                &ctx[(size_t)(b * Sq + qr0) * DD + h * DHH + c0]) =
                make_float2(acc[mt][nt][0], acc[mt][nt][1]);
            *reinterpret_cast<float2*>(
                &ctx[(size_t)(b * Sq + qr0 + 8) * DD + h * DHH + c0]) =
                make_float2(acc[mt][nt][2], acc[mt][nt][3]);
        }
    }
}

// ----------------------------------------------------------------------------
// out[row,:] = LayerNorm(a[row,:] + b[row,:]) * g + beta   (D = 1024)
// ----------------------------------------------------------------------------
__global__ __launch_bounds__(256) void add_ln_kernel(
    const float* __restrict__ a, const float* __restrict__ b,
    const float* __restrict__ g, const float* __restrict__ be,
    float* __restrict__ o)
{
    const int row = blockIdx.x;
    const int tid = threadIdx.x;
    const float* pa = a + (size_t)row * DD;
    const float* pb = b + (size_t)row * DD;

    __shared__ float red[8];
    float v[4];
    float s = 0.f;
#pragma unroll
    for (int i = 0; i < 4; i++) {
        int c = tid + i * 256;
        v[i] = pa[c] + pb[c];
        s += v[i];
    }
#pragma unroll
    for (int o2 = 16; o2; o2 >>= 1) s += __shfl_xor_sync(0xffffffffu, s, o2);
    if ((tid & 31) == 0) red[tid >> 5] = s;
    __syncthreads();
    if (tid < 32) {
        float t = (tid < 8) ? red[tid] : 0.f;
#pragma unroll
        for (int o2 = 4; o2; o2 >>= 1) t += __shfl_xor_sync(0xffffffffu, t, o2);
        if (tid == 0) red[0] = t;
    }
    __syncthreads();
    const float mu = red[0] * (1.f / 1024.f);
    __syncthreads();

    float s2 = 0.f;
#pragma unroll
    for (int i = 0; i < 4; i++) {
        float d = v[i] - mu;
        s2 += d * d;
    }
#pragma unroll
    for (int o2 = 16; o2; o2 >>= 1) s2 += __shfl_xor_sync(0xffffffffu, s2, o2);
    if ((tid & 31) == 0) red[tid >> 5] = s2;
    __syncthreads();
    if (tid < 32) {
        float t = (tid < 8) ? red[tid] : 0.f;
#pragma unroll
        for (int o2 = 4; o2; o2 >>= 1) t += __shfl_xor_sync(0xffffffffu, t, o2);
        if (tid == 0) red[0] = t;
    }
    __syncthreads();
    const float rstd = rsqrtf(red[0] * (1.f / 1024.f) + LN_EPS);

#pragma unroll
    for (int i = 0; i < 4; i++) {
        int c = tid + i * 256;
        o[(size_t)row * DD + c] = (v[i] - mu) * rstd * g[c] + be[c];
    }
}

// ----------------------------------------------------------------------------
// Host launch
// ----------------------------------------------------------------------------
static void launch_gemm(const float* A, const float* B, const float* bias,
                        float* C, int M, int N, int K, bool relu)
{
    dim3 grid(N / 128, M / 128);
    if (relu)
        gemm_tf32_kernel<1><<<grid, 256, GEMM_SMEM>>>(A, B, bias, C, M, N, K);
    else
        gemm_tf32_kernel<0><<<grid, 256, GEMM_SMEM>>>(A, B, bias, C, M, N, K);
}

static void pack_cols(const float* src, float* dst, int R, int C, int ldD)
{
    copy_cols_kernel<<<dim3((C + 255) / 256, R), 256>>>(src, dst, R, C, ldD);
}

extern "C" void kernel_launch(void* const* d_in, const int* in_sizes, int n_in,
                              void* d_out, int out_size)
{
    cudaFuncSetAttribute(gemm_tf32_kernel<0>,
                         cudaFuncAttributeMaxDynamicSharedMemorySize, GEMM_SMEM);
    cudaFuncSetAttribute(gemm_tf32_kernel<1>,
                         cudaFuncAttributeMaxDynamicSharedMemorySize, GEMM_SMEM);
    cudaFuncSetAttribute(attn_scores_tf32,
                         cudaFuncAttributeMaxDynamicSharedMemorySize, SCORES_SMEM);
    cudaFuncSetAttribute(attn_v_tf32,
                         cudaFuncAttributeMaxDynamicSharedMemorySize, ATTNV_SMEM);

    const float* x      = (const float*)d_in[0];
    const float* enc    = (const float*)d_in[1];
    const float* causal = (const float*)d_in[2];
    const float* pmask  = (const float*)d_in[3];
    (void)causal;

    const float* m1_wq = (const float*)d_in[4];
    const float* m1_qb = (const float*)d_in[5];
    const float* m1_wk = (const float*)d_in[6];
    const float* m1_kb = (const float*)d_in[7];
    const float* m1_wv = (const float*)d_in[8];
    const float* m1_vb = (const float*)d_in[9];
    const float* m1_wo = (const float*)d_in[10];
    const float* m1_ob = (const float*)d_in[11];

    const float* m2_wq = (const float*)d_in[12];
    const float* m2_qb = (const float*)d_in[13];
    const float* m2_wk = (const float*)d_in[14];
    const float* m2_kb = (const float*)d_in[15];
    const float* m2_wv = (const float*)d_in[16];
    const float* m2_vb = (const float*)d_in[17];
    const float* m2_wo = (const float*)d_in[18];
    const float* m2_ob = (const float*)d_in[19];

    const float* ffn_w1 = (const float*)d_in[20];
    const float* ffn_b1 = (const float*)d_in[21];
    const float* ffn_w2 = (const float*)d_in[22];
    const float* ffn_b2 = (const float*)d_in[23];

    const float* ln1_g = (const float*)d_in[24];
    const float* ln1_b = (const float*)d_in[25];
    const float* ln2_g = (const float*)d_in[26];
    const float* ln2_b = (const float*)d_in[27];
    const float* ln3_g = (const float*)d_in[28];
    const float* ln3_b = (const float*)d_in[29];

    float* out = (float*)d_out;

    float *q, *qkv, *wpk, *ctx, *t0, *x1, *y, *ffn, *scores;
    cudaGetSymbolAddress((void**)&q,      g_q);
    cudaGetSymbolAddress((void**)&qkv,    g_qkv);
    cudaGetSymbolAddress((void**)&wpk,    g_wpk);
    cudaGetSymbolAddress((void**)&ctx,    g_ctx);
    cudaGetSymbolAddress((void**)&t0,     g_t0);
    cudaGetSymbolAddress((void**)&x1,     g_x1);
    cudaGetSymbolAddress((void**)&y,      g_y);
    cudaGetSymbolAddress((void**)&ffn,    g_ffn);
    cudaGetSymbolAddress((void**)&scores, g_scores);

    float* bias3 = wpk + 3 * DD * DD;       // [3*DD] packed biases (+1*DD spare)

    const size_t OUTN = (size_t)BB * SS * DD;
    const size_t ATT  = (size_t)BB * HH * SS * SS;
    float* attn1 = ((size_t)out_size >= OUTN + ATT)     ? out + OUTN       : scores;
    float* attn2 = ((size_t)out_size >= OUTN + 2 * ATT) ? out + OUTN + ATT : scores;

    const int BS = BB * SS;
    const int BE = BB * EE;
    const int nrowsAttn = BB * HH * SS;

    // ---------------- MHA1 (masked self-attention) ----------------
    // Pack wq|wk|wv -> [DD][3*DD], biases -> [3*DD]; one fused GEMM N=3072.
    pack_cols(m1_wq, wpk + 0 * DD, DD, DD, 3 * DD);
    pack_cols(m1_wk, wpk + 1 * DD, DD, DD, 3 * DD);
    pack_cols(m1_wv, wpk + 2 * DD, DD, DD, 3 * DD);
    cudaMemcpyAsync(bias3 + 0 * DD, m1_qb, DD * 4, cudaMemcpyDeviceToDevice);
    cudaMemcpyAsync(bias3 + 1 * DD, m1_kb, DD * 4, cudaMemcpyDeviceToDevice);
    cudaMemcpyAsync(bias3 + 2 * DD, m1_vb, DD * 4, cudaMemcpyDeviceToDevice);
    launch_gemm(x, wpk, bias3, qkv, BS, 3 * DD, DD, false);

    attn_scores_tf32<<<dim3(SS / 128, SS / 128, BB * HH), 256, SCORES_SMEM>>>(
        qkv + 0 * DD, 3 * DD, qkv + 1 * DD, 3 * DD,
        pmask, /*mask_mode=*/0, attn1, SS, SS);
    softmax_rows_kernel<<<nrowsAttn / 8, dim3(32, 8)>>>(attn1, nrowsAttn, /*causal=*/1);
    attn_v_tf32<<<dim3(SS / 128, BB * HH), 256, ATTNV_SMEM>>>(
        attn1, qkv + 2 * DD, 3 * DD, ctx, SS, SS, /*mask_mode=*/0);

    launch_gemm(ctx, m1_wo, m1_ob, t0, BS, DD, DD, false);
    add_ln_kernel<<<BS, 256>>>(x, t0, ln1_g, ln1_b, x1);

    // ---------------- MHA2 (cross-attention) ----------------
    // q from x1 (separate GEMM), k|v fused from enc (N=2048, reuses qkv buf).
    launch_gemm(x1, m2_wq, m2_qb, q, BS, DD, DD, false);
    pack_cols(m2_wk, wpk + 0 * DD, DD, DD, 2 * DD);
    pack_cols(m2_wv, wpk + 1 * DD, DD, DD, 2 * DD);
    cudaMemcpyAsync(bias3 + 0 * DD, m2_kb, DD * 4, cudaMemcpyDeviceToDevice);
    cudaMemcpyAsync(bias3 + 1 * DD, m2_vb, DD * 4, cudaMemcpyDeviceToDevice);
    launch_gemm(enc, wpk, bias3, qkv, BE, 2 * DD, DD, false);

    attn_scores_tf32<<<dim3(EE / 128, SS / 128, BB * HH), 256, SCORES_SMEM>>>(
        q, DD, qkv + 0 * DD, 2 * DD,
        pmask, /*mask_mode=*/1, attn2, SS, EE);
    softmax_rows_kernel<<<nrowsAttn / 8, dim3(32, 8)>>>(attn2, nrowsAttn, /*causal=*/0);
    attn_v_tf32<<<dim3(SS / 128, BB * HH), 256, ATTNV_SMEM>>>(
        attn2, qkv + 1 * DD, 2 * DD, ctx, SS, EE, /*mask_mode=*/1);

    launch_gemm(ctx, m2_wo, m2_ob, t0, BS, DD, DD, false);
    add_ln_kernel<<<BS, 256>>>(t0, x1, ln2_g, ln2_b, y);

    // ---------------- FFN ----------------
    launch_gemm(y, ffn_w1, ffn_b1, ffn, BS, DFF, DD, true);
    launch_gemm(ffn, ffn_w2, ffn_b2, t0, BS, DD, DFF, false);
    add_ln_kernel<<<BS, 256>>>(y, t0, ln3_g, ln3_b, out);
}

// round 12
// speedup vs baseline: 1.0474x; 1.0474x over previous
#include <cuda_runtime.h>
#include <cuda_bf16.h>
#include <math.h>
#include <stdint.h>

// Problem constants
#define BB 4
#define SS 1024
#define EE 1024
#define DD 1024
#define HH 16
#define DHH 64
#define DFF 4096
#define LN_EPS 1e-6f

// ----------------------------------------------------------------------------
// Scratch (static device globals; no allocations allowed)
// ----------------------------------------------------------------------------
__device__ float g_q   [BB * SS * DD];
__device__ float g_qkv [BB * SS * 3 * DD];      // fused QKV / KV outputs
__device__ float g_wpk [3 * DD * DD + 4 * DD];  // packed (rounded) weights + biases
__device__ float g_wr  [11 * 1024 * 1024];      // rounded weights: wo1,wq2,wo2,w1,w2
__device__ float g_xr  [BB * SS * DD];          // rounded x
__device__ float g_encr[BB * EE * DD];          // rounded enc
__device__ float g_x1r [BB * SS * DD];          // rounded x1
__device__ float g_yr  [BB * SS * DD];          // rounded y
__device__ float g_ctx [BB * SS * DD];
__device__ float g_t0  [BB * SS * DD];
__device__ float g_x1  [BB * SS * DD];
__device__ float g_y   [BB * SS * DD];
__device__ float g_ffn [BB * SS * DFF];
__device__ float g_scores[(size_t)BB * HH * SS * SS];

// ----------------------------------------------------------------------------
// Helpers. All GEMM operands are pre-rounded to tf32 (RNA) in gmem, so inner
// loops feed raw fp32 bit patterns to mma — numerically identical to cvt.rna
// per fragment, with zero ALU cost in the hot loop.
// ----------------------------------------------------------------------------
__device__ __forceinline__ unsigned cvt_tf32(float x) {
    unsigned r;
    asm("cvt.rna.tf32.f32 %0, %1;" : "=r"(r) : "f"(x));
    return r;
}
__device__ __forceinline__ float round_tf32(float x) {
    return __uint_as_float(cvt_tf32(x));
}

__device__ __forceinline__ void mma_tf32(float* d, const unsigned* a,
                                         const unsigned* b, const float* c) {
    asm("mma.sync.aligned.m16n8k8.row.col.f32.tf32.tf32.f32 "
        "{%0,%1,%2,%3}, {%4,%5,%6,%7}, {%8,%9}, {%10,%11,%12,%13};"
        : "=f"(d[0]), "=f"(d[1]), "=f"(d[2]), "=f"(d[3])
        : "r"(a[0]), "r"(a[1]), "r"(a[2]), "r"(a[3]),
          "r"(b[0]), "r"(b[1]),
          "f"(c[0]), "f"(c[1]), "f"(c[2]), "f"(c[3]));
}

__device__ __forceinline__ void cp_async16(void* smem, const void* gmem) {
    unsigned saddr = (unsigned)__cvta_generic_to_shared(smem);
    asm volatile("cp.async.cg.shared.global [%0], [%1], 16;" :: "r"(saddr), "l"(gmem));
}
#define CP_COMMIT() asm volatile("cp.async.commit_group;")
__device__ __forceinline__ void cp_wait0() { asm volatile("cp.async.wait_group 0;"); }
__device__ __forceinline__ void cp_wait1() { asm volatile("cp.async.wait_group 1;"); }

// ----------------------------------------------------------------------------
// Elementwise tf32 rounding copy (float4 vectorized). n % 1024 == 0.
// ----------------------------------------------------------------------------
__global__ __launch_bounds__(256) void round_copy_kernel(
    const float* __restrict__ in, float* __restrict__ out, int n)
{
    int i = (blockIdx.x * 256 + threadIdx.x) * 4;
    if (i < n) {
        float4 v = *reinterpret_cast<const float4*>(&in[i]);
        v.x = round_tf32(v.x); v.y = round_tf32(v.y);
        v.z = round_tf32(v.z); v.w = round_tf32(v.w);
        *reinterpret_cast<float4*>(&out[i]) = v;
    }
}

// ----------------------------------------------------------------------------
// Strided column copy with tf32 rounding: dst[r*ldD + c] = round(src[r*C + c])
// ----------------------------------------------------------------------------
__global__ __launch_bounds__(256) void copy_cols_kernel(
    const float* __restrict__ src, float* __restrict__ dst, int R, int C, int ldD)
{
    int c = blockIdx.x * 256 + threadIdx.x;
    int r = blockIdx.y;
    if (c < C) dst[(size_t)r * ldD + c] = round_tf32(src[(size_t)r * C + c]);
}

// ----------------------------------------------------------------------------
// TF32 GEMM, 2-stage cp.async pipeline, raw-bit fragments.
// C[M,N] = A[M,K] @ B[K,N] + bias[N]; RELU and/or tf32-rounded output.
// ----------------------------------------------------------------------------
#define GEMM_SMEM (2 * (128 * 36 + 32 * 136) * 4)
#define AS_OFF(st) ((st) * 128 * 36)
#define BS_OFF(st) (2 * 128 * 36 + (st) * 32 * 136)

template <int RELU, int RND>
__global__ __launch_bounds__(256, 2) void gemm_tf32_kernel(
    const float* __restrict__ A, const float* __restrict__ B,
    const float* __restrict__ bias, float* __restrict__ C,
    int M, int N, int K)
{
    extern __shared__ float sm[];

    const int tid  = threadIdx.x;
    const int wid  = tid >> 5;
    const int lane = tid & 31;
    const int g    = lane >> 2;
    const int tig  = lane & 3;
    const int warpM = wid & 3;
    const int warpN = wid >> 2;
    const int m0 = blockIdx.y * 128;
    const int n0 = blockIdx.x * 128;

    float acc[2][8][4];
#pragma unroll
    for (int mt = 0; mt < 2; mt++)
#pragma unroll
        for (int nt = 0; nt < 8; nt++)
#pragma unroll
            for (int i = 0; i < 4; i++) acc[mt][nt][i] = 0.f;

    auto load_stage = [&](int st, int k0) {
        float* As = sm + AS_OFF(st);
        float* Bs = sm + BS_OFF(st);
#pragma unroll
        for (int l = 0; l < 4; l++) {
            int idx = tid + l * 256;
            int m = idx >> 3, s = idx & 7;
            cp_async16(&As[m * 36 + s * 4], &A[(size_t)(m0 + m) * K + k0 + s * 4]);
        }
#pragma unroll
        for (int l = 0; l < 4; l++) {
            int idx = tid + l * 256;
            int kk = idx >> 5, s = idx & 31;
            cp_async16(&Bs[kk * 136 + s * 4], &B[(size_t)(k0 + kk) * N + n0 + s * 4]);
        }
        CP_COMMIT();
    };

    const int T = K >> 5;
    load_stage(0, 0);

    for (int t = 0; t < T; t++) {
        if (t + 1 < T) { load_stage((t + 1) & 1, (t + 1) << 5); cp_wait1(); }
        else           { cp_wait0(); }
        __syncthreads();

        const unsigned* As = reinterpret_cast<const unsigned*>(sm + AS_OFF(t & 1));
        const unsigned* Bs = reinterpret_cast<const unsigned*>(sm + BS_OFF(t & 1));
#pragma unroll
        for (int kk = 0; kk < 32; kk += 8) {
            unsigned af[2][4];
#pragma unroll
            for (int mt = 0; mt < 2; mt++) {
                int r = warpM * 32 + mt * 16 + g;
                af[mt][0] = As[r * 36 + kk + tig];
                af[mt][1] = As[(r + 8) * 36 + kk + tig];
                af[mt][2] = As[r * 36 + kk + tig + 4];
                af[mt][3] = As[(r + 8) * 36 + kk + tig + 4];
            }
            unsigned bf[8][2];
#pragma unroll
            for (int nt = 0; nt < 8; nt++) {
                int c = warpN * 64 + nt * 8 + g;
                bf[nt][0] = Bs[(kk + tig) * 136 + c];
                bf[nt][1] = Bs[(kk + tig + 4) * 136 + c];
            }
#pragma unroll
            for (int mt = 0; mt < 2; mt++)
#pragma unroll
                for (int nt = 0; nt < 8; nt++)
                    mma_tf32(acc[mt][nt], af[mt], bf[nt], acc[mt][nt]);
        }
        __syncthreads();
    }

#pragma unroll
    for (int mt = 0; mt < 2; mt++) {
        int r0 = m0 + warpM * 32 + mt * 16 + g;
#pragma unroll
        for (int nt = 0; nt < 8; nt++) {
            int c0 = n0 + warpN * 64 + nt * 8 + tig * 2;
            float b0 = bias[c0], b1 = bias[c0 + 1];
            float v0 = acc[mt][nt][0] + b0;
            float v1 = acc[mt][nt][1] + b1;
            float v2 = acc[mt][nt][2] + b0;
            float v3 = acc[mt][nt][3] + b1;
            if (RELU) {
                v0 = fmaxf(v0, 0.f); v1 = fmaxf(v1, 0.f);
                v2 = fmaxf(v2, 0.f); v3 = fmaxf(v3, 0.f);
            }
            if (RND) {
                v0 = round_tf32(v0); v1 = round_tf32(v1);
                v2 = round_tf32(v2); v3 = round_tf32(v3);
            }
            *reinterpret_cast<float2*>(&C[(size_t)r0 * N + c0])       = make_float2(v0, v1);
            *reinterpret_cast<float2*>(&C[(size_t)(r0 + 8) * N + c0]) = make_float2(v2, v3);
        }
    }
}

// ----------------------------------------------------------------------------
// Attention scores (raw-bit tf32 mma): S[bh,q,k] = (Q . K)*0.125 + mask*(-1e9)
// Q/K are pre-rounded (GEMM epilogue). Arbitrary row strides.
// Causal fully-masked tiles: no work, no store.
// ----------------------------------------------------------------------------
#define SCORES_SMEM (2 * 128 * 68 * 4)

__global__ __launch_bounds__(256, 2) void attn_scores_tf32(
    const float* __restrict__ Qf, int ldq,
    const float* __restrict__ Kf, int ldk,
    const float* __restrict__ pmask, int mask_mode,
    float* __restrict__ Sout, int Sq, int Skv)
{
    extern __shared__ float sm[];
    float* Qs = sm;
    float* Ks = sm + 128 * 68;

    const int tid  = threadIdx.x;
    const int wid  = tid >> 5;
    const int lane = tid & 31;
    const int g    = lane >> 2;
    const int tig  = lane & 3;
    const int warpM = wid & 3;
    const int warpN = wid >> 2;
    const int bh = blockIdx.z;
    const int b = bh >> 4, h = bh & 15;
    const int q0 = blockIdx.y * 128;
    const int k0 = blockIdx.x * 128;

    if (mask_mode == 0 && k0 > q0 + 127) return;

#pragma unroll
    for (int l = 0; l < 8; l++) {
        int idx = tid + l * 256;
        int m = idx >> 4, s = idx & 15;
        cp_async16(&Qs[m * 68 + s * 4],
                   &Qf[(size_t)(b * Sq + q0 + m) * ldq + h * DHH + s * 4]);
    }
#pragma unroll
    for (int l = 0; l < 8; l++) {
        int idx = tid + l * 256;
        int m = idx >> 4, s = idx & 15;
        cp_async16(&Ks[m * 68 + s * 4],
                   &Kf[(size_t)(b * Skv + k0 + m) * ldk + h * DHH + s * 4]);
    }
    CP_COMMIT();
    cp_wait0();
    __syncthreads();

    float acc[2][8][4];
#pragma unroll
    for (int mt = 0; mt < 2; mt++)
#pragma unroll
        for (int nt = 0; nt < 8; nt++)
#pragma unroll
            for (int i = 0; i < 4; i++) acc[mt][nt][i] = 0.f;

    const unsigned* Qu = reinterpret_cast<const unsigned*>(Qs);
    const unsigned* Ku = reinterpret_cast<const unsigned*>(Ks);
#pragma unroll
    for (int kk = 0; kk < 64; kk += 8) {
        unsigned af[2][4];
#pragma unroll
        for (int mt = 0; mt < 2; mt++) {
            int r = warpM * 32 + mt * 16 + g;
            af[mt][0] = Qu[r * 68 + kk + tig];
            af[mt][1] = Qu[(r + 8) * 68 + kk + tig];
            af[mt][2] = Qu[r * 68 + kk + tig + 4];
            af[mt][3] = Qu[(r + 8) * 68 + kk + tig + 4];
        }
        unsigned bf[8][2];
#pragma unroll
        for (int nt = 0; nt < 8; nt++) {
            int r = warpN * 64 + nt * 8 + g;
            bf[nt][0] = Ku[r * 68 + kk + tig];
            bf[nt][1] = Ku[r * 68 + kk + tig + 4];
        }
#pragma unroll
        for (int mt = 0; mt < 2; mt++)
#pragma unroll
            for (int nt = 0; nt < 8; nt++)
                mma_tf32(acc[mt][nt], af[mt], bf[nt], acc[mt][nt]);
    }

#pragma unroll
    for (int mt = 0; mt < 2; mt++) {
        int qr0 = q0 + warpM * 32 + mt * 16 + g;
#pragma unroll
        for (int nt = 0; nt < 8; nt++) {
            int kc0 = k0 + warpN * 64 + nt * 8 + tig * 2;
#pragma unroll
            for (int half = 0; half < 2; half++) {
                int q = qr0 + half * 8;
                float v0 = acc[mt][nt][half * 2 + 0] * 0.125f;
                float v1 = acc[mt][nt][half * 2 + 1] * 0.125f;
                if (mask_mode == 0) {
                    if (kc0 > q)     v0 -= 1e9f;
                    if (kc0 + 1 > q) v1 -= 1e9f;
                } else {
                    v0 += pmask[(size_t)b * Skv + kc0] * (-1e9f);
                    v1 += pmask[(size_t)b * Skv + kc0 + 1] * (-1e9f);
                }
                *reinterpret_cast<float2*>(&Sout[((size_t)bh * Sq + q) * Skv + kc0]) =
                    make_float2(v0, v1);
            }
        }
    }
}

// ----------------------------------------------------------------------------
// Row softmax, ncols = 1024. One warp per row. Writes tf32-rounded probs
// (they feed attn_v raw-bit). causal: truncated read + zero-fill.
// ----------------------------------------------------------------------------
__global__ __launch_bounds__(256) void softmax_rows_kernel(
    float* __restrict__ P, int nrows, int causal)
{
    int row = blockIdx.x * 8 + threadIdx.y;
    if (row >= nrows) return;
    float* p = P + (size_t)row * 1024;
    const int lane = threadIdx.x;
    const int q = row & (SS - 1);
    const int nChunk = causal ? ((q >> 5) + 1) : 32;

    float v[32];
    float mx = -INFINITY;
    for (int i = 0; i < nChunk; i++) {
        v[i] = p[lane + i * 32];
        mx = fmaxf(mx, v[i]);
    }
#pragma unroll
    for (int o = 16; o; o >>= 1) mx = fmaxf(mx, __shfl_xor_sync(0xffffffffu, mx, o));

    float sum = 0.f;
    for (int i = 0; i < nChunk; i++) {
        v[i] = __expf(v[i] - mx);
        sum += v[i];
    }
#pragma unroll
    for (int o = 16; o; o >>= 1) sum += __shfl_xor_sync(0xffffffffu, sum, o);
    float inv = 1.f / sum;
    for (int i = 0; i < nChunk; i++) p[lane + i * 32] = round_tf32(v[i] * inv);
    for (int i = nChunk; i < 32; i++) p[lane + i * 32] = 0.f;
}

// ----------------------------------------------------------------------------
// attn_v (raw-bit tf32 mma, 2-stage pipeline): ctx = P @ V  (per (b,h))
// P (softmax-rounded) and V (GEMM-epilogue-rounded) raw. ctx written rounded
// (it feeds the wo GEMM).
// ----------------------------------------------------------------------------
#define ATTNV_SMEM (2 * (128 * 36 + 32 * 72) * 4)
#define PS_OFF(st) ((st) * 128 * 36)
#define VS_OFF(st) (2 * 128 * 36 + (st) * 32 * 72)

__global__ __launch_bounds__(256, 2) void attn_v_tf32(
    const float* __restrict__ P, const float* __restrict__ Vf, int ldv,
    float* __restrict__ ctx, int Sq, int Skv, int mask_mode)
{
    extern __shared__ float sm[];

    const int tid  = threadIdx.x;
    const int wid  = tid >> 5;
    const int lane = tid & 31;
    const int g    = lane >> 2;
    const int tig  = lane & 3;
    const int warpM = wid & 3;
    const int warpN = wid >> 2;
    const int bh = blockIdx.y;
    const int b = bh >> 4, h = bh & 15;
    const int q0 = blockIdx.x * 128;

    const int kEnd = (mask_mode == 0) ? min(Skv, q0 + 128) : Skv;
    const int T = kEnd >> 5;

    float acc[2][4][4];
#pragma unroll
    for (int mt = 0; mt < 2; mt++)
#pragma unroll
        for (int nt = 0; nt < 4; nt++)
#pragma unroll
            for (int i = 0; i < 4; i++) acc[mt][nt][i] = 0.f;

    auto load_stage = [&](int st, int k0) {
        float* Ps = sm + PS_OFF(st);
        float* Vs = sm + VS_OFF(st);
#pragma unroll
        for (int l = 0; l < 4; l++) {
            int idx = tid + l * 256;
            int m = idx >> 3, s = idx & 7;
            cp_async16(&Ps[m * 36 + s * 4],
                       &P[((size_t)bh * Sq + q0 + m) * Skv + k0 + s * 4]);
        }
#pragma unroll
        for (int l = 0; l < 2; l++) {
            int idx = tid + l * 256;
            int kk = idx >> 4, s = idx & 15;
            cp_async16(&Vs[kk * 72 + s * 4],
                       &Vf[(size_t)(b * Skv + k0 + kk) * ldv + h * DHH + s * 4]);
        }
        CP_COMMIT();
    };

    load_stage(0, 0);

    for (int t = 0; t < T; t++) {
        if (t + 1 < T) { load_stage((t + 1) & 1, (t + 1) << 5); cp_wait1(); }
        else           { cp_wait0(); }
        __syncthreads();

        const unsigned* Ps = reinterpret_cast<const unsigned*>(sm + PS_OFF(t & 1));
        const unsigned* Vs = reinterpret_cast<const unsigned*>(sm + VS_OFF(t & 1));
#pragma unroll
        for (int kk = 0; kk < 32; kk += 8) {
            unsigned af[2][4];
#pragma unroll
            for (int mt = 0; mt < 2; mt++) {
                int r = warpM * 32 + mt * 16 + g;
                af[mt][0] = Ps[r * 36 + kk + tig];
                af[mt][1] = Ps[(r + 8) * 36 + kk + tig];
                af[mt][2] = Ps[r * 36 + kk + tig + 4];
                af[mt][3] = Ps[(r + 8) * 36 + kk + tig + 4];
            }
            unsigned bf[4][2];
#pragma unroll
            for (int nt = 0; nt < 4; nt++) {
                int c = warpN * 32 + nt * 8 + g;
                bf[nt][0] = Vs[(kk + tig) * 72 + c];
                bf[nt][1] = Vs[(kk + tig + 4) * 72 + c];
            }
#pragma unroll
            for (int mt = 0; mt < 2; mt++)
#pragma unroll
                for (int nt = 0; nt < 4; nt++)
                    mma_tf32(acc[mt][nt], af[mt], bf[nt], acc[mt][nt]);
        }
        __syncthreads();
    }

#pragma unroll
    for (int mt = 0; mt < 2; mt++) {
        int qr0 = q0 + warpM * 32 + mt * 16 + g;
#pragma unroll
        for (int nt = 0; nt < 4; nt++) {
            int c0 = warpN * 32 + nt * 8 + tig * 2;
            *reinterpret_cast<float2*>(
                &ctx[(size_t)(b * Sq + qr0) * DD + h * DHH + c0]) =
                make_float2(round_tf32(acc[mt][nt][0]), round_tf32(acc[mt][nt][1]));
            *reinterpret_cast<float2*>(
                &ctx[(size_t)(b * Sq + qr0 + 8) * DD + h * DHH + c0]) =
                make_float2(round_tf32(acc[mt][nt][2]), round_tf32(acc[mt][nt][3]));
        }
    }
}

// ----------------------------------------------------------------------------
// out[row,:] = LayerNorm(a[row,:] + b[row,:]) * g + beta   (D = 1024)
// Optional second output o_r: tf32-rounded copy (for downstream GEMM A-operand).
// ----------------------------------------------------------------------------
__global__ __launch_bounds__(256) void add_ln_kernel(
    const float* __restrict__ a, const float* __restrict__ b,
    const float* __restrict__ g, const float* __restrict__ be,
    float* __restrict__ o, float* __restrict__ o_r)
{
    const int row = blockIdx.x;
    const int tid = threadIdx.x;
    const float* pa = a + (size_t)row * DD;
    const float* pb = b + (size_t)row * DD;

    __shared__ float red[8];
    float v[4];
    float s = 0.f;
#pragma unroll
    for (int i = 0; i < 4; i++) {
        int c = tid + i * 256;
        v[i] = pa[c] + pb[c];
        s += v[i];
    }
#pragma unroll
    for (int o2 = 16; o2; o2 >>= 1) s += __shfl_xor_sync(0xffffffffu, s, o2);
    if ((tid & 31) == 0) red[tid >> 5] = s;
    __syncthreads();
    if (tid < 32) {
        float t = (tid < 8) ? red[tid] : 0.f;
#pragma unroll
        for (int o2 = 4; o2; o2 >>= 1) t += __shfl_xor_sync(0xffffffffu, t, o2);
        if (tid == 0) red[0] = t;
    }
    __syncthreads();
    const float mu = red[0] * (1.f / 1024.f);
    __syncthreads();

    float s2 = 0.f;
#pragma unroll
    for (int i = 0; i < 4; i++) {
        float d = v[i] - mu;
        s2 += d * d;
    }
#pragma unroll
    for (int o2 = 16; o2; o2 >>= 1) s2 += __shfl_xor_sync(0xffffffffu, s2, o2);
    if ((tid & 31) == 0) red[tid >> 5] = s2;
    __syncthreads();
    if (tid < 32) {
        float t = (tid < 8) ? red[tid] : 0.f;
#pragma unroll
        for (int o2 = 4; o2; o2 >>= 1) t += __shfl_xor_sync(0xffffffffu, t, o2);
        if (tid == 0) red[0] = t;
    }
    __syncthreads();
    const float rstd = rsqrtf(red[0] * (1.f / 1024.f) + LN_EPS);

#pragma unroll
    for (int i = 0; i < 4; i++) {
        int c = tid + i * 256;
        float r = (v[i] - mu) * rstd * g[c] + be[c];
        o[(size_t)row * DD + c] = r;
        if (o_r) o_r[(size_t)row * DD + c] = round_tf32(r);
    }
}

// ----------------------------------------------------------------------------
// Host launch
// ----------------------------------------------------------------------------
static void launch_gemm(const float* A, const float* B, const float* bias,
                        float* C, int M, int N, int K, bool relu, bool rnd)
{
    dim3 grid(N / 128, M / 128);
    if (relu) {
        if (rnd) gemm_tf32_kernel<1,1><<<grid, 256, GEMM_SMEM>>>(A, B, bias, C, M, N, K);
        else     gemm_tf32_kernel<1,0><<<grid, 256, GEMM_SMEM>>>(A, B, bias, C, M, N, K);
    } else {
        if (rnd) gemm_tf32_kernel<0,1><<<grid, 256, GEMM_SMEM>>>(A, B, bias, C, M, N, K);
        else     gemm_tf32_kernel<0,0><<<grid, 256, GEMM_SMEM>>>(A, B, bias, C, M, N, K);
    }
}

static void pack_cols(const float* src, float* dst, int R, int C, int ldD)
{
    copy_cols_kernel<<<dim3((C + 255) / 256, R), 256>>>(src, dst, R, C, ldD);
}

static void round_copy(const float* src, float* dst, int n)
{
    round_copy_kernel<<<(n / 4 + 255) / 256, 256>>>(src, dst, n);
}

extern "C" void kernel_launch(void* const* d_in, const int* in_sizes, int n_in,
                              void* d_out, int out_size)
{
    cudaFuncSetAttribute(gemm_tf32_kernel<0,0>,
                         cudaFuncAttributeMaxDynamicSharedMemorySize, GEMM_SMEM);
    cudaFuncSetAttribute(gemm_tf32_kernel<0,1>,
                         cudaFuncAttributeMaxDynamicSharedMemorySize, GEMM_SMEM);
    cudaFuncSetAttribute(gemm_tf32_kernel<1,0>,
                         cudaFuncAttributeMaxDynamicSharedMemorySize, GEMM_SMEM);
    cudaFuncSetAttribute(gemm_tf32_kernel<1,1>,
                         cudaFuncAttributeMaxDynamicSharedMemorySize, GEMM_SMEM);
    cudaFuncSetAttribute(attn_scores_tf32,
                         cudaFuncAttributeMaxDynamicSharedMemorySize, SCORES_SMEM);
    cudaFuncSetAttribute(attn_v_tf32,
                         cudaFuncAttributeMaxDynamicSharedMemorySize, ATTNV_SMEM);

    const float* x      = (const float*)d_in[0];
    const float* enc    = (const float*)d_in[1];
    const float* causal = (const float*)d_in[2];
    const float* pmask  = (const float*)d_in[3];
    (void)causal;

    const float* m1_wq = (const float*)d_in[4];
    const float* m1_qb = (const float*)d_in[5];
    const float* m1_wk = (const float*)d_in[6];
    const float* m1_kb = (const float*)d_in[7];
    const float* m1_wv = (const float*)d_in[8];
    const float* m1_vb = (const float*)d_in[9];
    const float* m1_wo = (const float*)d_in[10];
    const float* m1_ob = (const float*)d_in[11];

    const float* m2_wq = (const float*)d_in[12];
    const float* m2_qb = (const float*)d_in[13];
    const float* m2_wk = (const float*)d_in[14];
    const float* m2_kb = (const float*)d_in[15];
    const float* m2_wv = (const float*)d_in[16];
    const float* m2_vb = (const float*)d_in[17];
    const float* m2_wo = (const float*)d_in[18];
    const float* m2_ob = (const float*)d_in[19];

    const float* ffn_w1 = (const float*)d_in[20];
    const float* ffn_b1 = (const float*)d_in[21];
    const float* ffn_w2 = (const float*)d_in[22];
    const float* ffn_b2 = (const float*)d_in[23];

    const float* ln1_g = (const float*)d_in[24];
    const float* ln1_b = (const float*)d_in[25];
    const float* ln2_g = (const float*)d_in[26];
    const float* ln2_b = (const float*)d_in[27];
    const float* ln3_g = (const float*)d_in[28];
    const float* ln3_b = (const float*)d_in[29];

    float* out = (float*)d_out;

    float *q, *qkv, *wpk, *wr, *xr, *encr, *x1r, *yr;
    float *ctx, *t0, *x1, *y, *ffn, *scores;
    cudaGetSymbolAddress((void**)&q,      g_q);
    cudaGetSymbolAddress((void**)&qkv,    g_qkv);
    cudaGetSymbolAddress((void**)&wpk,    g_wpk);
    cudaGetSymbolAddress((void**)&wr,     g_wr);
    cudaGetSymbolAddress((void**)&xr,     g_xr);
    cudaGetSymbolAddress((void**)&encr,   g_encr);
    cudaGetSymbolAddress((void**)&x1r,    g_x1r);
    cudaGetSymbolAddress((void**)&yr,     g_yr);
    cudaGetSymbolAddress((void**)&ctx,    g_ctx);
    cudaGetSymbolAddress((void**)&t0,     g_t0);
    cudaGetSymbolAddress((void**)&x1,     g_x1);
    cudaGetSymbolAddress((void**)&y,      g_y);
    cudaGetSymbolAddress((void**)&ffn,    g_ffn);
    cudaGetSymbolAddress((void**)&scores, g_scores);

    float* bias3 = wpk + 3 * DD * DD;
    const int MM1 = 1024 * 1024;
    float* wo1r = wr + 0 * MM1;
    float* wq2r = wr + 1 * MM1;
    float* wo2r = wr + 2 * MM1;
    float* w1r  = wr + 3 * MM1;   // 4M elems
    float* w2r  = wr + 7 * MM1;   // 4M elems

    const size_t OUTN = (size_t)BB * SS * DD;
    const size_t ATT  = (size_t)BB * HH * SS * SS;
    float* attn1 = ((size_t)out_size >= OUTN + ATT)     ? out + OUTN       : scores;
    float* attn2 = ((size_t)out_size >= OUTN + 2 * ATT) ? out + OUTN + ATT : scores;

    const int BS = BB * SS;
    const int BE = BB * EE;
    const int nrowsAttn = BB * HH * SS;

    // ---- Pre-round all static GEMM operands (weights + inputs) ----
    round_copy(x,   xr,   BB * SS * DD);
    round_copy(enc, encr, BB * EE * DD);
    round_copy(m1_wo,  wo1r, DD * DD);
    round_copy(m2_wq,  wq2r, DD * DD);
    round_copy(m2_wo,  wo2r, DD * DD);
    round_copy(ffn_w1, w1r,  DD * DFF);
    round_copy(ffn_w2, w2r,  DFF * DD);

    // ---------------- MHA1 (masked self-attention) ----------------
    pack_cols(m1_wq, wpk + 0 * DD, DD, DD, 3 * DD);
    pack_cols(m1_wk, wpk + 1 * DD, DD, DD, 3 * DD);
    pack_cols(m1_wv, wpk + 2 * DD, DD, DD, 3 * DD);
    cudaMemcpyAsync(bias3 + 0 * DD, m1_qb, DD * 4, cudaMemcpyDeviceToDevice);
    cudaMemcpyAsync(bias3 + 1 * DD, m1_kb, DD * 4, cudaMemcpyDeviceToDevice);
    cudaMemcpyAsync(bias3 + 2 * DD, m1_vb, DD * 4, cudaMemcpyDeviceToDevice);
    launch_gemm(xr, wpk, bias3, qkv, BS, 3 * DD, DD, false, /*rnd=*/true);

    attn_scores_tf32<<<dim3(SS / 128, SS / 128, BB * HH), 256, SCORES_SMEM>>>(
        qkv + 0 * DD, 3 * DD, qkv + 1 * DD, 3 * DD,
        pmask, /*mask_mode=*/0, attn1, SS, SS);
    softmax_rows_kernel<<<nrowsAttn / 8, dim3(32, 8)>>>(attn1, nrowsAttn, /*causal=*/1);
    attn_v_tf32<<<dim3(SS / 128, BB * HH), 256, ATTNV_SMEM>>>(
        attn1, qkv + 2 * DD, 3 * DD, ctx, SS, SS, /*mask_mode=*/0);

    launch_gemm(ctx, wo1r, m1_ob, t0, BS, DD, DD, false, /*rnd=*/false);
    add_ln_kernel<<<BS, 256>>>(x, t0, ln1_g, ln1_b, x1, x1r);

    // ---------------- MHA2 (cross-attention) ----------------
    launch_gemm(x1r, wq2r, m2_qb, q, BS, DD, DD, false, /*rnd=*/true);
    pack_cols(m2_wk, wpk + 0 * DD, DD, DD, 2 * DD);
    pack_cols(m2_wv, wpk + 1 * DD, DD, DD, 2 * DD);
    cudaMemcpyAsync(bias3 + 0 * DD, m2_kb, DD * 4, cudaMemcpyDeviceToDevice);
    cudaMemcpyAsync(bias3 + 1 * DD, m2_vb, DD * 4, cudaMemcpyDeviceToDevice);
    launch_gemm(encr, wpk, bias3, qkv, BE, 2 * DD, DD, false, /*rnd=*/true);

    attn_scores_tf32<<<dim3(EE / 128, SS / 128, BB * HH), 256, SCORES_SMEM>>>(
        q, DD, qkv + 0 * DD, 2 * DD,
        pmask, /*mask_mode=*/1, attn2, SS, EE);
    softmax_rows_kernel<<<nrowsAttn / 8, dim3(32, 8)>>>(attn2, nrowsAttn, /*causal=*/0);
    attn_v_tf32<<<dim3(SS / 128, BB * HH), 256, ATTNV_SMEM>>>(
        attn2, qkv + 1 * DD, 2 * DD, ctx, SS, EE, /*mask_mode=*/1);

    launch_gemm(ctx, wo2r, m2_ob, t0, BS, DD, DD, false, /*rnd=*/false);
    add_ln_kernel<<<BS, 256>>>(t0, x1, ln2_g, ln2_b, y, yr);

    // ---------------- FFN ----------------
    launch_gemm(yr, w1r, ffn_b1, ffn, BS, DFF, DD, true, /*rnd=*/true);
    launch_gemm(ffn, w2r, ffn_b2, t0, BS, DD, DFF, false, /*rnd=*/false);
    add_ln_kernel<<<BS, 256>>>(y, t0, ln3_g, ln3_b, out, nullptr);
}